// round 4
// baseline (speedup 1.0000x reference)
#include <cuda_runtime.h>
#include <cuda_bf16.h>
#include <stdint.h>

// SparseMixerV2 forward, persistent TMA-bulk double-buffered pipeline.
//   sel = argmax(logits) (first occurrence)
//   masked_j iff (m - l_j)/max(|l_j|, m) > 0.2   [division-free: 0.2*f + l < m]
//   multiplier = (0.3333+0.6667) / sum_unmasked exp(l_j - m)
// rand_u is provably dead (sel == argmax(masked_gates) always: the max survives
// masking, and masking preserves unmasked values + first-occurrence tie-break).
//
// One row per thread. Tiles of 128 rows (32KB) are fetched by ONE
// cp.async.bulk per tile (mbarrier complete_tx) into LINEAR smem — zero
// per-thread producer instructions. Reads are conflict-free via XOR quad
// addressing (quad = c ^ (t&15); 1 LOP3 per LDS.128).

#define E 64
#define TPB 128
#define TILE 128
#define TILE_BYTES (TILE * E * 4)      // 32768
#define LOG2E 1.4426950408889634f

// smem layout (dynamic): [0,8) bar0, [8,16) bar1, [1024, 1024+64KB) two buffers
#define SMEM_BAR0 0
#define SMEM_BAR1 8
#define SMEM_BUF  1024
#define SMEM_TOTAL (SMEM_BUF + 2 * TILE_BYTES)

__device__ __forceinline__ void mbar_init(uint32_t bar, uint32_t count) {
    asm volatile("mbarrier.init.shared.b64 [%0], %1;" :: "r"(bar), "r"(count) : "memory");
}
__device__ __forceinline__ void mbar_expect_tx(uint32_t bar, uint32_t bytes) {
    asm volatile("mbarrier.arrive.expect_tx.shared.b64 _, [%0], %1;"
                 :: "r"(bar), "r"(bytes) : "memory");
}
__device__ __forceinline__ void mbar_wait(uint32_t bar, uint32_t parity) {
    uint32_t done;
    do {
        asm volatile("{\n\t.reg .pred p;\n\t"
                     "mbarrier.try_wait.parity.shared.b64 p, [%1], %2;\n\t"
                     "selp.b32 %0, 1, 0, p;\n\t}"
                     : "=r"(done) : "r"(bar), "r"(parity) : "memory");
    } while (!done);
}
__device__ __forceinline__ void bulk_copy(uint32_t dst_smem, const void* src, uint32_t bar) {
    asm volatile("cp.async.bulk.shared::cluster.global.mbarrier::complete_tx::bytes "
                 "[%0], [%1], %2, [%3];"
                 :: "r"(dst_smem), "l"(src), "r"((uint32_t)TILE_BYTES), "r"(bar)
                 : "memory");
}

__global__ void __launch_bounds__(TPB)
sparsemixer_tma(const float* __restrict__ logits,
                float* __restrict__ out,      // [0,N): sel, [N,2N): multiplier, [2N]: 0
                int N, int out_size)
{
    extern __shared__ float smem[];
    const uint32_t smem_base = (uint32_t)__cvta_generic_to_shared(smem);
    const int t = threadIdx.x;

    if (blockIdx.x == 0 && t == 0 && out_size > 2 * N)
        out[2 * N] = 0.0f;                         // balance_loss

    const int numTiles = N / TILE;
    int tile = blockIdx.x;
    if (tile >= numTiles) return;

    const uint32_t bar[2]  = { smem_base + SMEM_BAR0, smem_base + SMEM_BAR1 };
    const uint32_t bufA[2] = { smem_base + SMEM_BUF, smem_base + SMEM_BUF + TILE_BYTES };

    if (t == 0) { mbar_init(bar[0], 1); mbar_init(bar[1], 1); }
    __syncthreads();

    // prologue: fetch first tile into slot 0
    if (t == 0) {
        mbar_expect_tx(bar[0], TILE_BYTES);
        bulk_copy(bufA[0], logits + (size_t)tile * TILE * E, bar[0]);
    }

    // per-thread pre-rotated row base (bits 4..7 = t&15) for XOR quad reads
    const uint32_t rowrot[2] = { bufA[0] + (uint32_t)t * 256u + ((uint32_t)(t & 15) << 4),
                                 bufA[1] + (uint32_t)t * 256u + ((uint32_t)(t & 15) << 4) };

    int i = 0;
    for (; tile < numTiles; tile += gridDim.x, i++) {
        const int slot = i & 1;
        const int nextTile = tile + gridDim.x;
        if (t == 0 && nextTile < numTiles) {       // slot^1 is free (see barrier note below)
            mbar_expect_tx(bar[slot ^ 1], TILE_BYTES);
            bulk_copy(bufA[slot ^ 1], logits + (size_t)nextTile * TILE * E, bar[slot ^ 1]);
        }
        mbar_wait(bar[slot], (uint32_t)((i >> 1) & 1));

        // ---- gather my row: 16 LDS.128, XOR quad addressing (conflict-free) ----
        float4 v[16];
        const uint32_t rb = rowrot[slot];
        #pragma unroll
        for (int c = 0; c < 16; c++) {
            float4 tmp;
            asm volatile("ld.shared.v4.f32 {%0,%1,%2,%3}, [%4];"
                         : "=f"(tmp.x), "=f"(tmp.y), "=f"(tmp.z), "=f"(tmp.w)
                         : "r"(rb ^ ((uint32_t)c << 4)));
            v[c ^ (t & 15)] = tmp;                 // logical quad index
        }

        // ---- pass 1: row max ----
        float m = fmaxf(fmaxf(v[0].x, v[0].y), fmaxf(v[0].z, v[0].w));
        #pragma unroll
        for (int c = 1; c < 16; c++)
            m = fmaxf(m, fmaxf(fmaxf(v[c].x, v[c].y), fmaxf(v[c].z, v[c].w)));

        const float c0 = -m * LOG2E;               // exp(l-m) = ex2(l*log2e + c0)

        // ---- pass 2 (descending index): first-occurrence argmax + masked exp-sum ----
        float s = 0.0f;
        int   sel = 0;
        #define SM_ELEM(X, IDX) {                                            \
            const float x_ = (X);                                            \
            const float f_ = fmaxf(fabsf(x_), m);                            \
            float e_;                                                        \
            asm("ex2.approx.f32 %0, %1;" : "=f"(e_) : "f"(fmaf(x_, LOG2E, c0))); \
            if (fmaf(0.2f, f_, x_) >= m) s += e_;                            \
            if (x_ == m) sel = (IDX); }
        #pragma unroll
        for (int j = 15; j >= 0; j--) {
            SM_ELEM(v[j].w, 4 * j + 3)
            SM_ELEM(v[j].z, 4 * j + 2)
            SM_ELEM(v[j].y, 4 * j + 1)
            SM_ELEM(v[j].x, 4 * j + 0)
        }
        #undef SM_ELEM

        const int row = tile * TILE + t;
        const float mf1 = 0.3333f + 0.6667f;       // mask_for_one (always true-branch)
        out[row]     = (float)sel;
        out[N + row] = mf1 / s;

        // all reads of this slot done before its next overwrite (issued next iter)
        __syncthreads();
    }
}

extern "C" void kernel_launch(void* const* d_in, const int* in_sizes, int n_in,
                              void* d_out, int out_size)
{
    const float* logits = (const float*)d_in[0];   // d_in[1] = rand_u: dead
    float* out = (float*)d_out;

    const int N = in_sizes[0] / E;                 // 1048576
    const int numTiles = N / TILE;                 // 8192

    cudaFuncSetAttribute(sparsemixer_tma,
                         cudaFuncAttributeMaxDynamicSharedMemorySize, SMEM_TOTAL);

    int blocks = 3 * 148;                          // 3 blocks/SM (≈67KB smem each)
    if (blocks > numTiles) blocks = numTiles;

    sparsemixer_tma<<<blocks, TPB, SMEM_TOTAL>>>(logits, out, N, out_size);
}

// round 6
// speedup vs baseline: 6.6377x; 6.6377x over previous
#include <cuda_runtime.h>
#include <cuda_bf16.h>
#include <stdint.h>

// SparseMixerV2 forward — warp-private double-buffered cp.async pipelines.
//   sel = argmax(logits) (first occurrence)
//   masked_j iff (m - l_j)/max(|l_j|, m) > 0.2   [division-free: 0.2*f + l < m]
//   multiplier = (0.3333+0.6667) / sum_unmasked exp(l_j - m)
// rand_u is provably dead (sel == argmax(masked_gates) always: the max survives
// masking, and masking preserves unmasked values + first-occurrence tie-break).
//
// One warp per block, one row per thread, 32-row / 8KB tiles, 2-deep ring in
// STATIC smem. Zero block-level syncs — each warp is an independent pipeline
// (12 per SM). XOR swizzle (slot = col ^ (row&15)) keeps both STS (via
// cp.async) and per-thread-row LDS.128 conflict-free. NOTE: with the swizzled
// WRITE, the XOR-rotated READ address already de-swizzles — the loaded value
// IS logical quad c (v[c] = tmp; the round-5 bug was re-applying the XOR).

#define E 64
#define TPB 32
#define TILE 32
#define BUF_FLOATS (TILE * E)          // 2048 floats = 8KB
#define LOG2E 1.4426950408889634f

__device__ __forceinline__ void prefetch_tile(const float* __restrict__ logits,
                                              float* __restrict__ buf,
                                              int tile, int lane)
{
    const float4* g = reinterpret_cast<const float4*>(logits + (size_t)tile * TILE * E);
    #pragma unroll
    for (int i = 0; i < 16; i++) {
        int idx  = lane + i * 32;          // float4 index within the 512-float4 tile
        int row  = idx >> 4;               // 16 float4 per row
        int col  = idx & 15;
        int slot = col ^ (row & 15);       // XOR swizzle
        uint32_t dst = (uint32_t)__cvta_generic_to_shared(buf + row * E + slot * 4);
        asm volatile("cp.async.cg.shared.global [%0], [%1], 16;"
                     :: "r"(dst), "l"(g + idx) : "memory");
    }
    asm volatile("cp.async.commit_group;" ::: "memory");
}

__global__ void __launch_bounds__(TPB)
sparsemixer_warp(const float* __restrict__ logits,
                 float* __restrict__ out,      // [0,N): sel, [N,2N): multiplier, [2N]: 0
                 int N, int out_size)
{
    __shared__ float smem[2 * BUF_FLOATS];     // 16KB static
    const int t = threadIdx.x;                 // lane == thread

    if (blockIdx.x == 0 && t == 0 && out_size > 2 * N)
        out[2 * N] = 0.0f;                     // balance_loss

    const int numTiles = N / TILE;
    int tile = blockIdx.x;
    if (tile >= numTiles) return;

    prefetch_tile(logits, smem, tile, t);      // slot 0

    // pre-rotated per-thread row base (bits 4..7 = t&15) for XOR quad reads
    const uint32_t sbase = (uint32_t)__cvta_generic_to_shared(smem);
    const uint32_t rowrot0 = sbase + (uint32_t)t * 256u + ((uint32_t)(t & 15) << 4);

    int bufIdx = 0;
    for (; tile < numTiles; tile += gridDim.x) {
        const int nextTile = tile + gridDim.x;
        if (nextTile < numTiles) {             // slot^1 reads finished last iter (syncwarp)
            prefetch_tile(logits, smem + (bufIdx ^ 1) * BUF_FLOATS, nextTile, t);
            asm volatile("cp.async.wait_group 1;" ::: "memory");
        } else {
            asm volatile("cp.async.wait_group 0;" ::: "memory");
        }
        __syncwarp();                          // all lanes' cp.asyncs retired + visible

        // ---- gather my row: 16 LDS.128 ----
        // physical slot (t&15)^c holds logical quad ((t&15)^c)^(t&15) = c
        float4 v[16];
        const uint32_t rb = rowrot0 + (uint32_t)bufIdx * (BUF_FLOATS * 4u);
        #pragma unroll
        for (int c = 0; c < 16; c++) {
            float4 tmp;
            asm volatile("ld.shared.v4.f32 {%0,%1,%2,%3}, [%4];"
                         : "=f"(tmp.x), "=f"(tmp.y), "=f"(tmp.z), "=f"(tmp.w)
                         : "r"(rb ^ ((uint32_t)c << 4)));
            v[c] = tmp;                        // already de-swizzled (see note above)
        }

        // ---- pass 1: row max ----
        float m = fmaxf(fmaxf(v[0].x, v[0].y), fmaxf(v[0].z, v[0].w));
        #pragma unroll
        for (int c = 1; c < 16; c++)
            m = fmaxf(m, fmaxf(fmaxf(v[c].x, v[c].y), fmaxf(v[c].z, v[c].w)));

        const float c0 = -m * LOG2E;           // exp(l-m) = ex2(l*log2e + c0)

        // ---- pass 2 (descending index): first-occurrence argmax + masked exp-sum ----
        float s = 0.0f;
        int   sel = 0;
        #define SM_ELEM(X, IDX) {                                                \
            const float x_ = (X);                                                \
            const float f_ = fmaxf(fabsf(x_), m);                                \
            float e_;                                                            \
            asm("ex2.approx.f32 %0, %1;" : "=f"(e_) : "f"(fmaf(x_, LOG2E, c0))); \
            if (fmaf(0.2f, f_, x_) >= m) s += e_;                                \
            if (x_ == m) sel = (IDX); }
        #pragma unroll
        for (int j = 15; j >= 0; j--) {
            SM_ELEM(v[j].w, 4 * j + 3)
            SM_ELEM(v[j].z, 4 * j + 2)
            SM_ELEM(v[j].y, 4 * j + 1)
            SM_ELEM(v[j].x, 4 * j + 0)
        }
        #undef SM_ELEM

        const int row = tile * TILE + t;
        const float mf1 = 0.3333f + 0.6667f;   // mask_for_one (always true-branch)
        out[row]     = (float)sel;
        out[N + row] = mf1 / s;

        __syncwarp();                          // all lanes done reading this slot
        bufIdx ^= 1;
    }
}

extern "C" void kernel_launch(void* const* d_in, const int* in_sizes, int n_in,
                              void* d_out, int out_size)
{
    const float* logits = (const float*)d_in[0];   // d_in[1] = rand_u: dead
    float* out = (float*)d_out;

    const int N = in_sizes[0] / E;                 // 1048576
    const int numTiles = N / TILE;                 // 32768

    int blocks = 12 * 148;                         // 12 warp-pipelines per SM
    if (blocks > numTiles) blocks = numTiles;

    sparsemixer_warp<<<blocks, TPB>>>(logits, out, N, out_size);
}